// round 16
// baseline (speedup 1.0000x reference)
#include <cuda_runtime.h>
#include <cuda_fp16.h>
#include <cstdint>

// ---------------------------------------------------------------------------
// SinkhornAttention: BS=4, SEQ=4096, DM=1024, H=16, HD=64, BLK=128, NB=32
// ---------------------------------------------------------------------------
#define BS   4
#define SEQ  4096
#define DM   1024
#define NH   16
#define HD   64
#define BLKS 128
#define NB   32
#define ROWS (BS*SEQ)            // 16384
#define HID  (NH*HD)             // 1024
#define PERB (SEQ*HID)           // 4194304 (elements per batch)
#define PERBLK (BLKS*HID)        // 131072

// GEMM tiling: CTA 128x256, 8 warps (2M x 4N), warp tile 64x64, KC=64
#define TM 128
#define TN 256
#define KC 64
#define NCHUNK (DM / KC)            // 16
#define ROWB 144                    // 128B data + 16B pad per 64-k row
#define MATB_A (128 * ROWB)         // 18432
#define MATB_B (256 * ROWB)         // 36864
#define STAGE_BYTES (MATB_A + MATB_B)  // 55296
#define NSTAGE 3
#define GEMM_SMEM (NSTAGE * STAGE_BYTES)   // 165888

// Attention smem: Q 16KB @0, K 32KB @16384, V 32KB @49152
#define ATT_SMEM 81920

// blockmix smem: K rows 32 x (2048B + 16 pad) + perm 32*80
#define BM_KSTRIDE 2064
#define BM_PERM_OFF (32 * BM_KSTRIDE)        // 66048
#define BM_SMEM (BM_PERM_OFF + 32 * 80)      // 68608

// ---------------------------------------------------------------------------
// Scratch (device globals: allocation-free per harness rules)
// ---------------------------------------------------------------------------
__device__ float g_sortout[BS*NB*NB];
__device__ float g_perm   [BS*NB*NB];

__device__ __half g_a16[ROWS*DM];    // inputs_q fp16
__device__ __half g_q16[ROWS*HID];
__device__ __half g_k16[ROWS*HID];
__device__ __half g_v16[ROWS*HID];
__device__ __half g_sk16[ROWS*HID];
__device__ __half g_sv16[ROWS*HID];
__device__ __half g_x16[ROWS*HID];
__device__ __half g_wq16[HID*DM];    // transposed [n][k]
__device__ __half g_wk16[HID*DM];
__device__ __half g_wv16[HID*DM];
__device__ __half g_wo16[DM*HID];

// ---------------------------------------------------------------------------
// PTX helpers
// ---------------------------------------------------------------------------
__device__ __forceinline__ void cp16(uint32_t s, const void* g) {
    asm volatile("cp.async.cg.shared.global [%0], [%1], 16;" :: "r"(s), "l"(g));
}
#define CP_COMMIT() asm volatile("cp.async.commit_group;" ::: "memory")
#define CP_WAIT(n)  asm volatile("cp.async.wait_group %0;" :: "n"(n) : "memory")

__device__ __forceinline__ void ldsm4(uint32_t* r, uint32_t addr) {
    asm volatile("ldmatrix.sync.aligned.m8n8.x4.shared.b16 {%0,%1,%2,%3}, [%4];"
                 : "=r"(r[0]), "=r"(r[1]), "=r"(r[2]), "=r"(r[3]) : "r"(addr));
}
__device__ __forceinline__ void ldsm4t(uint32_t* r, uint32_t addr) {
    asm volatile("ldmatrix.sync.aligned.m8n8.x4.trans.shared.b16 {%0,%1,%2,%3}, [%4];"
                 : "=r"(r[0]), "=r"(r[1]), "=r"(r[2]), "=r"(r[3]) : "r"(addr));
}
__device__ __forceinline__ void mma16816(float* c, const uint32_t* a,
                                         uint32_t b0, uint32_t b1) {
    asm volatile("mma.sync.aligned.m16n8k16.row.col.f32.f16.f16.f32 "
                 "{%0,%1,%2,%3}, {%4,%5,%6,%7}, {%8,%9}, {%0,%1,%2,%3};"
                 : "+f"(c[0]), "+f"(c[1]), "+f"(c[2]), "+f"(c[3])
                 : "r"(a[0]), "r"(a[1]), "r"(a[2]), "r"(a[3]), "r"(b0), "r"(b1));
}
__device__ __forceinline__ uint32_t packh2(float a, float b) {
    __half2 h = __floats2half2_rn(a, b);
    return *(uint32_t*)&h;
}

// ---------------------------------------------------------------------------
// Convert fp32 -> fp16 (4x float4 per thread for MLP)
// ---------------------------------------------------------------------------
__global__ __launch_bounds__(256)
void to_half(const float* __restrict__ src, __half* __restrict__ dst, int n4) {
    int i = (blockIdx.x * 256 + threadIdx.x) * 4;
    #pragma unroll
    for (int j = 0; j < 4; j++) {
        if (i + j >= n4) return;
        float4 f = ((const float4*)src)[i + j];
        __half2 h0, h1;
        h0.x = __float2half_rn(f.x); h0.y = __float2half_rn(f.y);
        h1.x = __float2half_rn(f.z); h1.y = __float2half_rn(f.w);
        ((__half2*)dst)[(i + j) * 2]     = h0;
        ((__half2*)dst)[(i + j) * 2 + 1] = h1;
    }
}

// ---------------------------------------------------------------------------
// Transpose 4x 1024x1024 fp32 W[k][n] -> fp16 Wt[n][k], fused (grid.z selects)
// ---------------------------------------------------------------------------
__global__ __launch_bounds__(256)
void transpose_half4(const float* __restrict__ W0, const float* __restrict__ W1,
                     const float* __restrict__ W2, const float* __restrict__ W3,
                     __half* __restrict__ T0, __half* __restrict__ T1,
                     __half* __restrict__ T2, __half* __restrict__ T3) {
    const float* W = (blockIdx.z == 0) ? W0 : (blockIdx.z == 1) ? W1
                   : (blockIdx.z == 2) ? W2 : W3;
    __half* T = (blockIdx.z == 0) ? T0 : (blockIdx.z == 1) ? T1
              : (blockIdx.z == 2) ? T2 : T3;
    __shared__ float t[32][33];
    const int tx = threadIdx.x, ty = threadIdx.y;
    const int x = blockIdx.x * 32 + tx;
    const int y0 = blockIdx.y * 32;
    #pragma unroll
    for (int i = ty; i < 32; i += 8) t[i][tx] = W[(size_t)(y0 + i) * 1024 + x];
    __syncthreads();
    const int k = y0 + tx;
    #pragma unroll
    for (int i = ty; i < 32; i += 8) {
        int n = blockIdx.x * 32 + i;
        T[(size_t)n * 1024 + k] = __float2half_rn(t[tx][i]);
    }
}

// ---------------------------------------------------------------------------
// HMMA GEMM, KC=64, 3-stage cp.async, cross-k16 fragment double-buffering.
// grid.z selects (B, bias, out). fp32 out (Cf) when non-null else fp16 (Ch).
// ---------------------------------------------------------------------------
__global__ __launch_bounds__(256, 1)
void gemm_hmma(const __half* __restrict__ A,
               const __half* __restrict__ B0, const __half* __restrict__ B1,
               const __half* __restrict__ B2,
               const float* __restrict__ bi0, const float* __restrict__ bi1,
               const float* __restrict__ bi2,
               float* __restrict__ Cf,
               __half* __restrict__ Ch0, __half* __restrict__ Ch1,
               __half* __restrict__ Ch2) {
    const int z = blockIdx.z;
    const __half* __restrict__ B  = (z == 0) ? B0 : (z == 1) ? B1 : B2;
    const float* __restrict__ bias = (z == 0) ? bi0 : (z == 1) ? bi1 : bi2;
    __half* __restrict__ Ch = (z == 0) ? Ch0 : (z == 1) ? Ch1 : Ch2;

    extern __shared__ __align__(128) char smem[];
    const uint32_t sbase = (uint32_t)__cvta_generic_to_shared(smem);

    const int tid  = threadIdx.x;
    const int wid  = tid >> 5, lane = tid & 31;
    const int wm   = wid >> 2;
    const int wn   = wid & 3;
    const int bx0  = blockIdx.x * TN;
    const int by0  = blockIdx.y * TM;

    auto load_stage = [&](int c, int s) {
        const uint32_t st = sbase + (uint32_t)s * STAGE_BYTES;
        const size_t k0 = (size_t)c * KC;
        #pragma unroll
        for (int i = 0; i < 4; i++) {             // A: 128 rows x 8 chunks of 16B
            const int q = tid + i * 256;
            const int row = q >> 3, ch = q & 7;
            cp16(st + (uint32_t)(row * ROWB + ch * 16),
                 A + (size_t)(by0 + row) * DM + k0 + ch * 8);
        }
        #pragma unroll
        for (int i = 0; i < 8; i++) {             // B: 256 rows x 8 chunks
            const int q = tid + i * 256;
            const int row = q >> 3, ch = q & 7;
            cp16(st + MATB_A + (uint32_t)(row * ROWB + ch * 16),
                 B + (size_t)(bx0 + row) * DM + k0 + ch * 8);
        }
    };

    const int mi   = lane >> 3;
    const int lrow = lane & 7;
    const uint32_t aoff = (uint32_t)(((mi & 1) * 8 + lrow) * ROWB + (mi >> 1) * 16);
    const uint32_t boff = (uint32_t)(((mi >> 1) * 8 + lrow) * ROWB + (mi & 1) * 16);

    float acc[4][8][4];
    #pragma unroll
    for (int i = 0; i < 4; i++)
        #pragma unroll
        for (int j = 0; j < 8; j++)
            #pragma unroll
            for (int k = 0; k < 4; k++) acc[i][j][k] = 0.f;

    load_stage(0, 0); CP_COMMIT();
    load_stage(1, 1); CP_COMMIT();

    for (int c = 0; c < NCHUNK; c++) {
        CP_WAIT(1);
        __syncthreads();

        const uint32_t st = sbase + (uint32_t)(c % 3) * STAGE_BYTES;
        const uint32_t sA = st, sB = st + MATB_A;

        auto ldfrag = [&](int ks, uint32_t (&a)[4][4], uint32_t (&b)[4][4]) {
            const uint32_t kb = (uint32_t)ks * 32;
            #pragma unroll
            for (int mt = 0; mt < 4; mt++)
                ldsm4(a[mt], sA + (uint32_t)((wm * 64 + mt * 16) * ROWB) + kb + aoff);
            #pragma unroll
            for (int nb = 0; nb < 4; nb++)
                ldsm4(b[nb], sB + (uint32_t)((wn * 64 + nb * 16) * ROWB) + kb + boff);
        };

        uint32_t a[2][4][4], b[2][4][4];
        ldfrag(0, a[0], b[0]);

        #pragma unroll
        for (int ks = 0; ks < 4; ks++) {
            const int cur = ks & 1;
            if (ks < 3) ldfrag(ks + 1, a[cur ^ 1], b[cur ^ 1]);
            if (ks == 1) {
                if (c + 2 < NCHUNK) load_stage(c + 2, (c + 2) % 3);
                CP_COMMIT();
            }
            #pragma unroll
            for (int mt = 0; mt < 4; mt++)
                #pragma unroll
                for (int nt = 0; nt < 8; nt++) {
                    const int p = nt >> 1, q = (nt & 1) * 2;
                    mma16816(acc[mt][nt], a[cur][mt], b[cur][p][q], b[cur][p][q+1]);
                }
        }
    }

    const int g = lane >> 2, t2 = (lane & 3) * 2;
    #pragma unroll
    for (int mt = 0; mt < 4; mt++) {
        const int row0 = by0 + wm * 64 + mt * 16 + g;
        #pragma unroll
        for (int nt = 0; nt < 8; nt++) {
            const int col = bx0 + wn * 64 + nt * 8 + t2;
            const float2 bv = *(const float2*)(bias + col);
            float o00 = acc[mt][nt][0] + bv.x, o01 = acc[mt][nt][1] + bv.y;
            float o10 = acc[mt][nt][2] + bv.x, o11 = acc[mt][nt][3] + bv.y;
            if (Cf) {
                *(float2*)(Cf + (size_t)row0 * HID + col)       = make_float2(o00, o01);
                *(float2*)(Cf + (size_t)(row0 + 8) * HID + col) = make_float2(o10, o11);
            } else {
                *(uint32_t*)(Ch + (size_t)row0 * HID + col)       = packh2(o00, o01);
                *(uint32_t*)(Ch + (size_t)(row0 + 8) * HID + col) = packh2(o10, o11);
            }
        }
    }
}

// ---------------------------------------------------------------------------
// sum_key + sort logits: 512 threads, half2 columns, MLP-unrolled row loop
// ---------------------------------------------------------------------------
__global__ __launch_bounds__(512)
void sumkey_sort(const float* __restrict__ w_sort, const float* __restrict__ b_sort) {
    __shared__ float sk[HID];
    const int bn = blockIdx.x;
    const int b = bn >> 5, n = bn & 31;
    const int t = threadIdx.x;        // 0..511 = half2 column

    const __half2* base = (const __half2*)(g_k16 + ((size_t)(b * SEQ + n * BLKS)) * HID);
    float2 s0 = {0.f,0.f}, s1 = {0.f,0.f}, s2 = {0.f,0.f}, s3 = {0.f,0.f};
    #pragma unroll 8
    for (int r = 0; r < BLKS; r += 4) {
        float2 f0 = __half22float2(base[(size_t)(r+0) * 512 + t]);
        float2 f1 = __half22float2(base[(size_t)(r+1) * 512 + t]);
        float2 f2 = __half22float2(base[(size_t)(r+2) * 512 + t]);
        float2 f3 = __half22float2(base[(size_t)(r+3) * 512 + t]);
        s0.x += f0.x; s0.y += f0.y; s1.x += f1.x; s1.y += f1.y;
        s2.x += f2.x; s2.y += f2.y; s3.x += f3.x; s3.y += f3.y;
    }
    sk[t*2]   = (s0.x + s1.x) + (s2.x + s3.x);
    sk[t*2+1] = (s0.y + s1.y) + (s2.y + s3.y);
    __syncthreads();

    const int warp = t >> 5, lane = t & 31;
    for (int m = warp; m < NB; m += 16) {
        float s = 0.f;
        for (int c = lane; c < HID; c += 32) s += sk[c] * w_sort[c * NB + m];
        #pragma unroll
        for (int o = 16; o; o >>= 1) s += __shfl_xor_sync(0xffffffffu, s, o);
        if (lane == 0) g_sortout[b * (NB*NB) + n * NB + m] = s + b_sort[m];
    }
}

// ---------------------------------------------------------------------------
// Sinkhorn
// ---------------------------------------------------------------------------
__global__ void sinkhorn_kernel() {
    __shared__ float la[32][33];
    __shared__ float colLse[32];
    const int b = blockIdx.x;
    const int j = threadIdx.x, i = threadIdx.y;

    float v = g_sortout[b * (NB*NB) + i * NB + j];

    for (int it = 0; it < 5; it++) {
        float mx = v;
        #pragma unroll
        for (int o = 16; o; o >>= 1) mx = fmaxf(mx, __shfl_xor_sync(0xffffffffu, mx, o));
        float sum = expf(v - mx);
        #pragma unroll
        for (int o = 16; o; o >>= 1) sum += __shfl_xor_sync(0xffffffffu, sum, o);
        v -= mx + logf(sum);

        la[i][j] = v;
        __syncthreads();

        float cv = la[j][i];
        float cm = cv;
        #pragma unroll
        for (int o = 16; o; o >>= 1) cm = fmaxf(cm, __shfl_xor_sync(0xffffffffu, cm, o));
        float cs = expf(cv - cm);
        #pragma unroll
        for (int o = 16; o; o >>= 1) cs += __shfl_xor_sync(0xffffffffu, cs, o);
        if (j == 0) colLse[i] = cm + logf(cs);
        __syncthreads();

        v -= colLse[j];
        __syncthreads();
    }
    g_perm[b * (NB*NB) + i * NB + j] = expf(fminf(fmaxf(v, -1.f), 1.f));
}

// ---------------------------------------------------------------------------
// blockmix via HMMA (R13-proven): sorted[n][s] = perm[n][m] @ Kblk[m][s].
// ---------------------------------------------------------------------------
__global__ __launch_bounds__(256, 1)
void blockmix_mma() {
    extern __shared__ __align__(128) char sm[];
    const uint32_t sb = (uint32_t)__cvta_generic_to_shared(sm);
    const uint32_t sK = sb, sP = sb + BM_PERM_OFF;

    const int t0 = blockIdx.x;           // token within block (0..127)
    const int b  = blockIdx.y;
    const int which = blockIdx.z;
    const __half* __restrict__ src = which ? g_v16 : g_k16;
    __half* __restrict__ dst = which ? g_sv16 : g_sk16;

    const int tid = threadIdx.x;
    const int w = tid >> 5, lane = tid & 31;

    // stage K rows: row m = src[b, m*128 + t0, :], 1024 halves = 128 chunks of 16B
    #pragma unroll
    for (int i = 0; i < 16; i++) {
        const int q = tid + i * 256;             // 0..4095
        const int row = q >> 7, ch = q & 127;
        cp16(sK + row * BM_KSTRIDE + ch * 16,
             src + ((size_t)b * PERB + (size_t)row * PERBLK + (size_t)t0 * HID) + ch * 8);
    }
    // stage perm (fp32 -> fp16), 32x32, row stride 80B
    #pragma unroll
    for (int i = 0; i < 4; i++) {
        const int q = tid + i * 256;             // 0..1023
        const int row = q >> 5, col = q & 31;
        *(__half*)(sm + BM_PERM_OFF + row * 80 + col * 2) =
            __float2half_rn(g_perm[b * (NB*NB) + q]);
    }
    CP_COMMIT(); CP_WAIT(0);
    __syncthreads();

    const int mi = lane >> 3, lrow = lane & 7;
    const int g = lane >> 2, t2 = (lane & 3) * 2;

    // A frags: perm rows = n (M dim), cols = m (K dim): 2 m16 x 2 k16
    uint32_t ap[2][2][4];
    #pragma unroll
    for (int mt = 0; mt < 2; mt++)
        #pragma unroll
        for (int kk = 0; kk < 2; kk++)
            ldsm4(ap[mt][kk], sP + (uint32_t)((mt * 16 + (mi & 1) * 8 + lrow) * 80
                                              + (kk * 2 + (mi >> 1)) * 16));

    // per warp: 128 s-cols (w*128 ..), 8 s16-groups
    float acc[2][16][4];
    #pragma unroll
    for (int i = 0; i < 2; i++)
        #pragma unroll
        for (int j = 0; j < 16; j++)
            #pragma unroll
            for (int k = 0; k < 4; k++) acc[i][j][k] = 0.f;

    const int brow_c = (mi & 1) * 8 + lrow;      // row within 16-m group (trans)
    #pragma unroll
    for (int sg = 0; sg < 8; sg++) {             // 16 s-cols per group
        const int ch = w * 16 + sg * 2 + (mi >> 1);  // 16B chunk index
        #pragma unroll
        for (int kk = 0; kk < 2; kk++) {
            uint32_t bb[4];
            ldsm4t(bb, sK + (uint32_t)((kk * 16 + brow_c) * BM_KSTRIDE) + ch * 16);
            #pragma unroll
            for (int mt = 0; mt < 2; mt++) {
                mma16816(acc[mt][sg*2],   ap[mt][kk], bb[0], bb[1]);
                mma16816(acc[mt][sg*2+1], ap[mt][kk], bb[2], bb[3]);
            }
        }
    }

    // store: row n = mt*16 + g (+8 for c2,c3), col = w*128 + nt*8 + t2
    #pragma unroll
    for (int mt = 0; mt < 2; mt++) {
        const int n0 = mt * 16 + g;
        #pragma unroll
        for (int nt = 0; nt < 16; nt++) {
            const int col = w * 128 + nt * 8 + t2;
            const size_t d0 = (size_t)b * PERB + (size_t)n0 * PERBLK
                            + (size_t)t0 * HID + col;
            *(uint32_t*)(dst + d0)                      = packh2(acc[mt][nt][0], acc[mt][nt][1]);
            *(uint32_t*)(dst + d0 + (size_t)8 * PERBLK) = packh2(acc[mt][nt][2], acc[mt][nt][3]);
        }
    }
}

// ---------------------------------------------------------------------------
// Block attention, fp16 HMMA. R15: chunked cp.async staging (9 commit groups:
// Q, K0..K3, V0..V3) with incremental waits so K/V stream in under compute.
// Arithmetic identical to R13/R14.
// ---------------------------------------------------------------------------
__global__ __launch_bounds__(256, 2)
void attn_kernel() {
    extern __shared__ __align__(128) char sm[];
    const uint32_t sb = (uint32_t)__cvta_generic_to_shared(sm);
    const uint32_t sQ = sb, sK = sb + 16384, sV = sb + 49152;

    const int h = blockIdx.x, n = blockIdx.y, b = blockIdx.z;
    const int t = threadIdx.x;
    const int w = t >> 5, lane = t & 31;

    // ---- group 1: Q (128 rows x 8 chunks)
    const __half* qg = g_q16 + ((size_t)(b * SEQ + n * BLKS)) * HID + h * HD;
    #pragma unroll
    for (int i = 0; i < 4; i++) {
        const int task = t + i * 256;
        const int row = task >> 3, ch = task & 7;
        cp16(sQ + row * 128 + (((ch ^ row) & 7) << 4), qg + (size_t)row * HID + ch * 8);
    }
    CP_COMMIT();

    // ---- groups 2..5: K in 4 chunks of 64 rows
    #pragma unroll
    for (int c4 = 0; c4 < 4; c4++) {
        #pragma unroll
        for (int i = 0; i < 2; i++) {
            const int task = t + i * 256;            // 0..511
            const int row = c4 * 64 + (task >> 3), ch = task & 7;
            const __half* kp = (row < BLKS)
                ? g_k16 + ((size_t)(b * SEQ + n * BLKS + row)) * HID + h * HD
                : g_sk16 + (size_t)b * PERB + (size_t)n * PERBLK + (size_t)(row - BLKS) * HID + h * HD;
            cp16(sK + row * 128 + (((ch ^ row) & 7) << 4), kp + ch * 8);
        }
        CP_COMMIT();
    }

    // ---- groups 6..9: V in 4 chunks of 64 rows
    #pragma unroll
    for (int c4 = 0; c4 < 4; c4++) {
        #pragma unroll
        for (int i = 0; i < 2; i++) {
            const int task = t + i * 256;
            const int row = c4 * 64 + (task >> 3), ch = task & 7;
            const __half* vp = (row < BLKS)
                ? g_v16 + ((size_t)(b * SEQ + n * BLKS + row)) * HID + h * HD
                : g_sv16 + (size_t)b * PERB + (size_t)n * PERBLK + (size_t)(row - BLKS) * HID + h * HD;
            cp16(sV + row * 128 + (((ch ^ row) & 7) << 4), vp + ch * 8);
        }
        CP_COMMIT();
    }

    const int mi = lane >> 3, lrow = lane & 7;
    const int g = lane >> 2, t2 = (lane & 3) * 2;

    // ---- Q fragments: only group 1 must be complete (<=8 pending)
    CP_WAIT(8);
    __syncthreads();
    uint32_t qa[4][4];
    {
        const int qrow = w * 16 + (mi & 1) * 8 + lrow;
        const uint32_t qb = sQ + qrow * 128;
        const int qsw = qrow & 7;
        #pragma unroll
        for (int kt = 0; kt < 4; kt++) {
            const int ch = kt * 2 + (mi >> 1);
            ldsm4(qa[kt], qb + ((ch ^ qsw) << 4));
        }
    }

    float of[8][4];
    #pragma unroll
    for (int i = 0; i < 8; i++)
        #pragma unroll
        for (int j = 0; j < 4; j++) of[i][j] = 0.f;
    float M0 = -1e30f, M1 = -1e30f, p0 = 0.f, p1 = 0.f;

    const int krow_c = (mi >> 1) * 8 + lrow;
    const int vrow_c = (mi & 1) * 8 + lrow;

    for (int kc = 0; kc < 4; kc++) {
        // K[kc] is group 2+kc: complete when <= 7-kc groups pending
        switch (kc) {
            case 0: CP_WAIT(7); break;
            case 1: CP_WAIT(6); break;
            case 2: CP_WAIT(5); break;
            default: CP_WAIT(4); break;
        }
        __syncthreads();

        float sc[8][4];
        #pragma unroll
        for (int i = 0; i < 8; i++)
            #pragma unroll
            for (int j = 0; j < 4; j++) sc[i][j] = 0.f;

        #pragma unroll
        for (int kt = 0; kt < 4; kt++) {
            #pragma unroll
            for (int ng = 0; ng < 4; ng++) {
                const int krow = kc * 64 + ng * 16 + krow_c;
                const int ch = kt * 2 + (mi & 1);
                uint32_t kb[4];
                ldsm4(kb, sK + krow * 128 + (((ch ^ krow) & 7) << 4));
                mma16816(sc[ng*2],   qa[kt], kb[0], kb[1]);
                mma16816(sc[ng*2+1], qa[kt], kb[2], kb[3]);
            }
        }
        #pragma unroll
        for (int i = 0; i < 8; i++)
            #pragma unroll
            for (int j = 0; j < 4; j++) sc[i][j] *= 0.125f;

        float m0 = -1e30f, m1 = -1e30f;
        #pragma unroll
        for (int i = 0; i < 8; i++) {
            m0 = fmaxf(m0, fmaxf(sc[i][0], sc[i][1]));
            m1 = fmaxf(m1, fmaxf(sc[i][2], sc[i][3]));
        }
        m0 = fmaxf(m0, __shfl_xor_sync(0xffffffffu, m0, 1));
        m0 = fmaxf(m0, __shfl_xor_sync(0xffffffffu, m0, 2));
        m1 = fmaxf(m1, __shfl_xor_sync(0xffffffffu, m1, 1));
        m1 = fmaxf(m1, __shfl_xor_sync(0xffffffffu, m1, 2));

        const float nM0 = fmaxf(M0, m0), nM1 = fmaxf(M1, m1);
        const float c0 = __expf(M0 - nM0), c1 = __expf(M1 - nM1);
        p0 *= c0; p1 *= c1;
        #pragma unroll
        for (int i = 0; i < 8; i++) {
            of[i][0] *= c0; of[i][1] *= c0;
            of[i][2] *= c1; of[i][3] *= c1;
        }
        M0 = nM0; M1 = nM1;

        #pragma unroll
        for (int i = 0; i < 8; i++) {
            sc[i][0] = __expf(sc[i][0] - M0);
            sc[i][1] = __expf(sc[i][1] - M0);
            sc[i][2] = __expf(sc[i][2] - M1);
            sc[i][3] = __expf(sc[i][3] - M1);
            p0 += sc[i][0] + sc[i][1];
            p1 += sc[i][2] + sc[i][3];
        }

        // V[kc] is group 6+kc: complete when <= 3-kc groups pending
        switch (kc) {
            case 0: CP_WAIT(3); break;
            case 1: CP_WAIT(2); break;
            case 2: CP_WAIT(1); break;
            default: CP_WAIT(0); break;
        }
        __syncthreads();

        #pragma unroll
        for (int kt = 0; kt < 4; kt++) {
            uint32_t pa[4];
            pa[0] = packh2(sc[2*kt][0],   sc[2*kt][1]);
            pa[1] = packh2(sc[2*kt][2],   sc[2*kt][3]);
            pa[2] = packh2(sc[2*kt+1][0], sc[2*kt+1][1]);
            pa[3] = packh2(sc[2*kt+1][2], sc[2*kt+1][3]);
            const int vrow = kc * 64 + kt * 16 + vrow_c;
            const uint32_t vb_base = sV + vrow * 128;
            const int vsw = vrow & 7;
            #pragma unroll
            for (int dg = 0; dg < 4; dg++) {
                const int ch = dg * 2 + (mi >> 1);
                uint32_t vb[4];
                ldsm4t(vb, vb_base + ((ch ^ vsw) << 4));
                mma16816(of[dg*2],   pa, vb[0], vb[1]);
                mma16816(of[dg*2+1], pa, vb[2], vb[3]);
            }
        }
    }

    p0 += __shfl_xor_sync(0xffffffffu, p0, 1);
    p0 += __shfl_xor_sync(0xffffffffu, p0, 2);
    p1 += __shfl_xor_sync(0xffffffffu, p1, 1);
    p1 += __shfl_xor_sync(0xffffffffu, p1, 2);
    const float i0 = 1.f / p0, i1 = 1.f / p1;

    const size_t o0 = ((size_t)(b * SEQ + n * BLKS + w * 16 + g)) * HID + h * HD;
    const size_t o1 = o0 + (size_t)8 * HID;
    #pragma unroll
    for (int dg = 0; dg < 8; dg++) {
        *(uint32_t*)(g_x16 + o0 + dg * 8 + t2) = packh2(of[dg][0] * i0, of[dg][1] * i0);
        *(uint32_t*)(g_x16 + o1 + dg * 8 + t2) = packh2(of[dg][2] * i1, of[dg][3] * i1);
    }
}

// ---------------------------------------------------------------------------
// Host launcher
// ---------------------------------------------------------------------------
extern "C" void kernel_launch(void* const* d_in, const int* in_sizes, int n_in,
                              void* d_out, int out_size) {
    const float* inputs_q = (const float*)d_in[0];
    const float* wq = (const float*)d_in[1];
    const float* bq = (const float*)d_in[2];
    const float* wk = (const float*)d_in[3];
    const float* bk = (const float*)d_in[4];
    const float* wv = (const float*)d_in[5];
    const float* bv = (const float*)d_in[6];
    const float* w_sort = (const float*)d_in[7];
    const float* b_sort = (const float*)d_in[8];
    const float* wo = (const float*)d_in[9];
    const float* bo = (const float*)d_in[10];
    float* out = (float*)d_out;

    __half *a16, *q16, *k16, *v16, *x16, *wq16, *wk16, *wv16, *wo16;
    cudaGetSymbolAddress((void**)&a16,  g_a16);
    cudaGetSymbolAddress((void**)&q16,  g_q16);
    cudaGetSymbolAddress((void**)&k16,  g_k16);
    cudaGetSymbolAddress((void**)&v16,  g_v16);
    cudaGetSymbolAddress((void**)&x16,  g_x16);
    cudaGetSymbolAddress((void**)&wq16, g_wq16);
    cudaGetSymbolAddress((void**)&wk16, g_wk16);
    cudaGetSymbolAddress((void**)&wv16, g_wv16);
    cudaGetSymbolAddress((void**)&wo16, g_wo16);

    cudaFuncSetAttribute(gemm_hmma, cudaFuncAttributeMaxDynamicSharedMemorySize, GEMM_SMEM);
    cudaFuncSetAttribute(attn_kernel, cudaFuncAttributeMaxDynamicSharedMemorySize, ATT_SMEM);
    cudaFuncSetAttribute(blockmix_mma, cudaFuncAttributeMaxDynamicSharedMemorySize, BM_SMEM);

    const int n4 = ROWS * DM / 4;
    to_half<<<(n4 / 4 + 255) / 256, 256>>>(inputs_q, a16, n4);
    transpose_half4<<<dim3(32, 32, 4), dim3(32, 8)>>>(wq, wk, wv, wo,
                                                      wq16, wk16, wv16, wo16);

    // Fused Q/K/V projection: grid.z selects weight/bias/output
    gemm_hmma<<<dim3(HID / TN, ROWS / TM, 3), 256, GEMM_SMEM>>>(
        a16, wq16, wk16, wv16, bq, bk, bv, nullptr, q16, k16, v16);

    sumkey_sort<<<BS * NB, 512>>>(w_sort, b_sort);
    sinkhorn_kernel<<<BS, dim3(32, 32)>>>();
    blockmix_mma<<<dim3(BLKS, BS, 2), 256, BM_SMEM>>>();
    attn_kernel<<<dim3(NH, NB, BS), 256, ATT_SMEM>>>();

    // Output projection (fp32 out)
    gemm_hmma<<<dim3(HID / TN, ROWS / TM, 1), 256, GEMM_SMEM>>>(
        x16, wo16, wo16, wo16, bo, bo, bo, out, nullptr, nullptr, nullptr);
}